// round 12
// baseline (speedup 1.0000x reference)
#include <cuda_runtime.h>
#include <cstdint>

#define NB 64
#define SL 510
#define SLP 532
#define NT 9
#define HID 768
#define FULLM 0xffffffffu

__device__ float g_emiss[NB * SLP * NT];   // zero-init; pad rows stay 0
__device__ float g_val[NB];
__device__ unsigned g_cnt;                 // zero-init; returns to 0 each call

__device__ __forceinline__ void fma2(unsigned long long& d,
                                     unsigned long long a,
                                     unsigned long long b) {
    asm("fma.rn.f32x2 %0, %1, %2, %3;" : "=l"(d) : "l"(a), "l"(b), "l"(d));
}
__device__ __forceinline__ float lo32(unsigned long long a) {
    return __uint_as_float((unsigned)a);
}
__device__ __forceinline__ float hi32(unsigned long long a) {
    return __uint_as_float((unsigned)(a >> 32));
}
__device__ __forceinline__ float p2f(int d) {
    return (d > -126) ? __int_as_float((127 + d) << 23) : 0.f;
}

// ---------------------------------------------------------------------------
// Kernel A (round-8 exact): 4 rows/warp, 8-lane K-split, f32x2 FMA,
// weight smem broadcast-deduped.
// ---------------------------------------------------------------------------
__global__ __launch_bounds__(256) void emis_kernel(
    const float* __restrict__ hidden,
    const float* __restrict__ weight,
    const float* __restrict__ bias) {
    __shared__ ulonglong2 ws2[NT * 192];
    __shared__ float bs[NT];

    int tid = threadIdx.x;
    for (int i = tid; i < NT * 192; i += 256)
        ws2[i] = ((const ulonglong2*)weight)[i];
    if (tid < NT) bs[tid] = bias[tid];
    __syncthreads();

    int lane = tid & 31;
    int q = lane >> 3;
    int sub = lane & 7;
    int w = blockIdx.x * 8 + (tid >> 5);
    int r = w * 4 + q;
    int b = r / SL;
    int s = r - b * SL;

    const ulonglong2* hp =
        (const ulonglong2*)(hidden + (size_t)(b * 512 + s + 1) * HID);

    unsigned long long acc2[NT];
#pragma unroll
    for (int t = 0; t < NT; t++) acc2[t] = 0ull;

#pragma unroll
    for (int p = 0; p < 2; p++) {
        ulonglong2 h[12];
#pragma unroll
        for (int u = 0; u < 12; u++) h[u] = hp[p * 96 + u * 8 + sub];
#pragma unroll
        for (int u = 0; u < 12; u++) {
#pragma unroll
            for (int t = 0; t < NT; t++) {
                ulonglong2 wv = ws2[t * 192 + p * 96 + u * 8 + sub];
                fma2(acc2[t], h[u].x, wv.x);
                fma2(acc2[t], h[u].y, wv.y);
            }
        }
    }

    float acc[NT];
#pragma unroll
    for (int t = 0; t < NT; t++) acc[t] = lo32(acc2[t]) + hi32(acc2[t]);
#pragma unroll
    for (int t = 0; t < NT; t++) {
#pragma unroll
        for (int off = 4; off > 0; off >>= 1)
            acc[t] += __shfl_xor_sync(FULLM, acc[t], off);
    }

    float* o = g_emiss + ((size_t)b * SLP + s) * NT;
#pragma unroll
    for (int t = 0; t < NT; t++) {
        int wsub = (t == 8) ? 0 : t;
        if (sub == wsub) o[t] = acc[t] + bs[t];
    }
}

// ---------------------------------------------------------------------------
// Kernel B: fully-merged CRF. 64 blocks (one per batch) x 768 threads.
// Phase A (24 warps): dual-semiring segment matrices (8 segs x 64 steps).
// Combine: warp 0 = denominator, warp 1 = Viterbi boundary vectors.
// Replay: warps 0-7 (exact hist) while warp 8 does the numerator.
// Finalize: warp 0 backtrack + output; last block reduces -llh.
// ---------------------------------------------------------------------------
__global__ __launch_bounds__(768) void crf_kernel(
    const int* __restrict__ labels,
    const float* __restrict__ start_t,
    const float* __restrict__ end_t,
    const float* __restrict__ trans,
    float* __restrict__ out) {
    __shared__ int s_lbl[528];
    __shared__ unsigned char hist[512 * 12];
    __shared__ float s_Mp[8][108];     // plus-times matrices (row stride 12)
    __shared__ float s_Mm[8][108];     // max-plus matrices
    __shared__ float s_bnd[8][12];
    __shared__ float s_fin[12];
    __shared__ int s_E[24];
    __shared__ float s_den, s_num;

    int b = blockIdx.x;
    int tid = threadIdx.x;
    int wid = tid >> 5;
    int lane = tid & 31;

    const float* em_base = g_emiss + (size_t)b * SLP * NT;
    const int* lbl = labels + b * 512;

    for (int i = tid; i < 511; i += 768) s_lbl[i] = lbl[i];
    if (tid >= 511 && tid < 528) s_lbl[tid] = -1;
    __syncthreads();

    // =================== PHASE A: dual-semiring chains ====================
    {
        int seg = wid / 3;
        int tpl = wid - seg * 3;
        int gq = lane / 9;
        int lj9 = lane - gq * 9;
        bool a27 = lane < 27;
        int row = tpl * 3 + gq;
        int gbase = gq * 9;
        int ss0 = 1 + seg * 64;

        float tra[NT], texp[NT];
#pragma unroll
        for (int k = 0; k < NT; k++) {
            tra[k] = trans[k * NT + lj9];
            texp[k] = __expf(tra[k]);
        }
        float stP = (a27 && lj9 == row) ? 1.f : 0.f;
        float stM = (a27 && lj9 == row) ? 0.f : -1e30f;
        int acc_e = 0;

        float em_cur[8], pe_cur[8], em_nxt[8];
#pragma unroll
        for (int u = 0; u < 8; u++)
            em_cur[u] = a27 ? em_base[(ss0 + u) * NT + lj9] : -1e30f;
#pragma unroll
        for (int u = 0; u < 8; u++) pe_cur[u] = __expf(em_cur[u]);
#pragma unroll
        for (int u = 0; u < 8; u++)
            em_nxt[u] = a27 ? em_base[(ss0 + 8 + u) * NT + lj9] : -1e30f;

        for (int gg = 0; gg < 8; ++gg) {
#pragma unroll
            for (int u = 0; u < 8; ++u) {
                int s = ss0 + gg * 8 + u;
                float em_c = em_cur[u];
                float pe_c = pe_cur[u];
                em_cur[u] = em_nxt[u];
                pe_cur[u] = __expf(em_nxt[u]);
                em_nxt[u] = a27 ? em_base[(s + 16) * NT + lj9] : -1e30f;
                int m = s_lbl[s + 1] >= 0;

                float p0 = __shfl_sync(FULLM, stP, gbase + 0);
                float p1 = __shfl_sync(FULLM, stP, gbase + 1);
                float p2 = __shfl_sync(FULLM, stP, gbase + 2);
                float p3 = __shfl_sync(FULLM, stP, gbase + 3);
                float p4 = __shfl_sync(FULLM, stP, gbase + 4);
                float p5 = __shfl_sync(FULLM, stP, gbase + 5);
                float p6 = __shfl_sync(FULLM, stP, gbase + 6);
                float p7 = __shfl_sync(FULLM, stP, gbase + 7);
                float p8 = __shfl_sync(FULLM, stP, gbase + 8);

                float x0 = __shfl_sync(FULLM, stM, gbase + 0) + tra[0];
                float x1 = __shfl_sync(FULLM, stM, gbase + 1) + tra[1];
                float x2 = __shfl_sync(FULLM, stM, gbase + 2) + tra[2];
                float x3 = __shfl_sync(FULLM, stM, gbase + 3) + tra[3];
                float x4 = __shfl_sync(FULLM, stM, gbase + 4) + tra[4];
                float x5 = __shfl_sync(FULLM, stM, gbase + 5) + tra[5];
                float x6 = __shfl_sync(FULLM, stM, gbase + 6) + tra[6];
                float x7 = __shfl_sync(FULLM, stM, gbase + 7) + tra[7];
                float x8 = __shfl_sync(FULLM, stM, gbase + 8) + tra[8];

                float d0 = fmaf(p6, texp[6], fmaf(p3, texp[3], p0 * texp[0]));
                float d1 = fmaf(p7, texp[7], fmaf(p4, texp[4], p1 * texp[1]));
                float d2 = fmaf(p8, texp[8], fmaf(p5, texp[5], p2 * texp[2]));
                float nvP = ((d0 + d1) + d2) * pe_c;
                stP = (m && a27) ? nvP : stP;

                float mA = fmaxf(fmaxf(fmaxf(x0, x1), fmaxf(x2, x3)),
                                 fmaxf(fmaxf(x4, x5), fmaxf(x6, fmaxf(x7, x8))));
                stM = (m && a27) ? (mA + em_c) : stM;
            }
            float mx = stP;
#pragma unroll
            for (int off = 16; off > 0; off >>= 1)
                mx = fmaxf(mx, __shfl_xor_sync(FULLM, mx, off));
            int Eb = (__float_as_int(mx) >> 23) & 0xff;
            int Es = Eb ? Eb : 127;
            stP *= __int_as_float((254 - Es) << 23);
            acc_e += Es - 127;
        }
        if (a27) {
            s_Mp[seg][row * 12 + lj9] = stP;
            s_Mm[seg][row * 12 + lj9] = stM;
        }
        if (lane == 0) s_E[seg * 3 + tpl] = acc_e;
    }
    __syncthreads();

    bool act = lane < 9;
    int lj = act ? lane : 0;

    // =================== COMBINE (warps 0 and 1 in parallel) ==============
    if (wid == 0) {
        // denominator: v = v x P_seg with exponent tracking
        float v = act ? __expf(start_t[lane] + em_base[lane]) : 0.f;
        int acc = 0;
        for (int sg = 0; sg < 8; ++sg) {
            float vi[9];
#pragma unroll
            for (int i = 0; i < 9; i++) vi[i] = __shfl_sync(FULLM, v, i);
            const float* M = s_Mp[sg];
            float q0 = vi[0]*M[0*12+lj] + vi[1]*M[1*12+lj] + vi[2]*M[2*12+lj];
            float q1 = vi[3]*M[3*12+lj] + vi[4]*M[4*12+lj] + vi[5]*M[5*12+lj];
            float q2 = vi[6]*M[6*12+lj] + vi[7]*M[7*12+lj] + vi[8]*M[8*12+lj];
            int E0 = s_E[sg*3+0], E1 = s_E[sg*3+1], E2 = s_E[sg*3+2];
            int Em = max(E0, max(E1, E2));
            float nv = q0 * p2f(E0 - Em) + q1 * p2f(E1 - Em)
                     + q2 * p2f(E2 - Em);
            acc += Em;
            float ref = __shfl_sync(FULLM, nv, 4);
            int Rb = (__float_as_int(ref) >> 23) & 0xff;
            int Rs = Rb ? Rb : 127;
            nv *= __int_as_float((254 - Rs) << 23);
            acc += Rs - 127;
            v = act ? nv : 0.f;
        }
        float fa = act ? v * __expf(end_t[lane]) : 0.f;
        fa += __shfl_xor_sync(FULLM, fa, 8);
        fa += __shfl_xor_sync(FULLM, fa, 4);
        fa += __shfl_xor_sync(FULLM, fa, 2);
        fa += __shfl_xor_sync(FULLM, fa, 1);
        if (lane == 0)
            s_den = __logf(fa) + (float)acc * 0.69314718056f;
    } else if (wid == 1) {
        // Viterbi boundary vectors
        float v = act ? (start_t[lane] + em_base[lane]) : -1e30f;
        if (act) s_bnd[0][lane] = v;
        for (int sg = 0; sg < 8; ++sg) {
            float vi[9];
#pragma unroll
            for (int i = 0; i < 9; i++) vi[i] = __shfl_sync(FULLM, v, i);
            const float* M = s_Mm[sg];
            float c0 = fmaxf(vi[0] + M[0*12+lj], vi[1] + M[1*12+lj]);
            float c1 = fmaxf(vi[2] + M[2*12+lj], vi[3] + M[3*12+lj]);
            float c2 = fmaxf(vi[4] + M[4*12+lj], vi[5] + M[5*12+lj]);
            float c3 = fmaxf(vi[6] + M[6*12+lj],
                      fmaxf(vi[7] + M[7*12+lj], vi[8] + M[8*12+lj]));
            float nv = fmaxf(fmaxf(c0, c1), fmaxf(c2, c3));
            v = act ? nv : -1e30f;
            if (act && sg < 7) s_bnd[sg + 1][lane] = v;
        }
    }
    __syncthreads();

    // =================== REPLAY (warps 0-7) + NUMERATOR (warp 8) ==========
    if (wid < 8) {
        int sg = wid;
        int ss = 1 + sg * 64;
        float tr[NT];
#pragma unroll
        for (int k = 0; k < NT; k++) tr[k] = trans[k * NT + lj];
        float vs = act ? s_bnd[sg][lane] : -1e30f;

        float em2[8];
#pragma unroll
        for (int u = 0; u < 8; u++)
            em2[u] = act ? em_base[(ss + u) * NT + lane] : 0.f;

        for (int gg = 0; gg < 8; ++gg) {
#pragma unroll
            for (int u = 0; u < 8; ++u) {
                int s = ss + gg * 8 + u;
                float em_c = em2[u];
                em2[u] = act ? em_base[(s + 8) * NT + lane] : 0.f;
                int m = s_lbl[s + 1] >= 0;

                float x0 = __shfl_sync(FULLM, vs, 0) + tr[0];
                float x1 = __shfl_sync(FULLM, vs, 1) + tr[1];
                float x2 = __shfl_sync(FULLM, vs, 2) + tr[2];
                float x3 = __shfl_sync(FULLM, vs, 3) + tr[3];
                float x4 = __shfl_sync(FULLM, vs, 4) + tr[4];
                float x5 = __shfl_sync(FULLM, vs, 5) + tr[5];
                float x6 = __shfl_sync(FULLM, vs, 6) + tr[6];
                float x7 = __shfl_sync(FULLM, vs, 7) + tr[7];
                float x8 = __shfl_sync(FULLM, vs, 8) + tr[8];

                float mA = fmaxf(fmaxf(fmaxf(x0, x1), fmaxf(x2, x3)),
                                 fmaxf(fmaxf(x4, x5),
                                       fmaxf(x6, fmaxf(x7, x8))));
                vs = (m && act) ? (mA + em_c) : vs;

                int bi = 8;
                if (x7 == mA) bi = 7;
                if (x6 == mA) bi = 6;
                if (x5 == mA) bi = 5;
                if (x4 == mA) bi = 4;
                if (x3 == mA) bi = 3;
                if (x2 == mA) bi = 2;
                if (x1 == mA) bi = 1;
                if (x0 == mA) bi = 0;

                if (act)
                    hist[(s - 1) * 12 + lane] = (unsigned char)(m ? bi : lane);
            }
        }
        if (sg == 7 && act) s_fin[lane] = vs;
    } else if (wid == 8) {
        // numerator: order-free parallel sum
        int t0 = lane * 16;
        float sum = 0.f;
        int prev = -1, ftag = -1;
        for (int k = 0; k < 16; ++k) {
            int t = t0 + k;
            if (t == 0 || t > 509) continue;
            int lv = s_lbl[t + 1];
            if (lv >= 0) {
                sum += em_base[t * NT + lv];
                if (prev >= 0) sum += trans[prev * NT + lv];
                else ftag = lv;
                prev = lv;
            }
        }
        int l1 = s_lbl[1];
        int tag0 = (l1 >= 0) ? l1 : 0;

        int x = prev;
#pragma unroll
        for (int off = 1; off < 32; off <<= 1) {
            int y = __shfl_up_sync(FULLM, x, off);
            if (lane >= off && x < 0) x = y;
        }
        int excl = __shfl_up_sync(FULLM, x, 1);
        int carry = (lane == 0 || excl < 0) ? tag0 : excl;

        if (ftag >= 0) sum += trans[carry * NT + ftag];
        if (lane == 0) sum += start_t[tag0] + em_base[tag0];
        if (lane == 31) sum += end_t[(x < 0) ? tag0 : x];

#pragma unroll
        for (int off = 16; off > 0; off >>= 1)
            sum += __shfl_xor_sync(FULLM, sum, off);
        if (lane == 0) s_num = sum;
    }
    __syncthreads();

    // =================== FINALIZE (warp 0) ================================
    if (wid == 0) {
        float fv = act ? (s_fin[lane] + end_t[lane]) : -1e30f;
        int fi = act ? lane : 15;
#pragma unroll
        for (int off = 8; off > 0; off >>= 1) {
            float ov = __shfl_xor_sync(FULLM, fv, off);
            int oi = __shfl_xor_sync(FULLM, fi, off);
            bool take = (ov > fv) || (ov == fv && oi < fi);
            fv = take ? ov : fv;
            fi = take ? oi : fi;
        }
        int last = __shfl_sync(FULLM, fi, 0);
        __syncwarp();

        int a = lane * 16;
        int bnd2 = a + 16 < (SL - 1) ? a + 16 : (SL - 1);
        unsigned long long F = 0x876543210ull;
        for (int s = bnd2 - 1; s >= a; --s) {
            const unsigned char* hr = hist + s * 12;
            unsigned long long nF = 0;
#pragma unroll
            for (int t = 0; t < NT; t++) {
                int e = (int)((F >> (4 * t)) & 15);
                nF |= ((unsigned long long)hr[e]) << (4 * t);
            }
            F = nF;
        }
        unsigned int flo = (unsigned int)F, fhi = (unsigned int)(F >> 32);
        int cur = last;
        int my_entry = (lane == 31) ? last : 0;
        for (int l = 31; l >= 1; --l) {
            unsigned int lo = __shfl_sync(FULLM, flo, l);
            unsigned int hi = __shfl_sync(FULLM, fhi, l);
            unsigned long long Fl = ((unsigned long long)hi << 32) | lo;
            cur = (int)((Fl >> (4 * cur)) & 15);
            if (lane == l - 1) my_entry = cur;
        }

        float* otag = out + 1 + (size_t)b * SL;
        if (lane == 31) otag[SL - 1] = (s_lbl[SL] >= 0) ? (float)last : 0.f;
        int c2 = my_entry;
        for (int s = bnd2 - 1; s >= a; --s) {
            c2 = hist[s * 12 + c2];
            otag[s] = (s_lbl[s + 1] >= 0) ? (float)c2 : 0.f;
        }

        // ---- per-batch value + last-block global reduce ----
        if (lane == 0) {
            g_val[b] = s_num - s_den;
            __threadfence();
            unsigned old = atomicAdd(&g_cnt, 1u);
            if (old == NB - 1) {
                __threadfence();
                float sum = 0.f;
                const volatile float* gv = g_val;
#pragma unroll
                for (int i = 0; i < NB; i++) sum += gv[i];
                out[0] = -sum;
                atomicSub(&g_cnt, (unsigned)NB);   // restore for next launch
            }
        }
    }
}

// ---------------------------------------------------------------------------
extern "C" void kernel_launch(void* const* d_in, const int* in_sizes, int n_in,
                              void* d_out, int out_size) {
    const float* hidden  = (const float*)d_in[0];
    const int*   labels  = (const int*)d_in[1];
    const float* weight  = (const float*)d_in[2];
    const float* bias    = (const float*)d_in[3];
    const float* start_t = (const float*)d_in[4];
    const float* end_t   = (const float*)d_in[5];
    const float* trans   = (const float*)d_in[6];
    float* out = (float*)d_out;

    emis_kernel<<<1020, 256>>>(hidden, weight, bias);
    crf_kernel<<<NB, 768>>>(labels, start_t, end_t, trans, out);
}

// round 13
// speedup vs baseline: 1.1531x; 1.1531x over previous
#include <cuda_runtime.h>
#include <cstdint>

#define NB 64
#define SL 510
#define SLP 532
#define NT 9
#define HID 768
#define FULLM 0xffffffffu

__device__ float g_emiss[NB * SLP * NT];   // zero-init; pad rows stay 0
__device__ float g_val[NB];
__device__ unsigned g_cnt;                 // zero-init; restored each call

__device__ __forceinline__ void fma2(unsigned long long& d,
                                     unsigned long long a,
                                     unsigned long long b) {
    asm("fma.rn.f32x2 %0, %1, %2, %3;" : "=l"(d) : "l"(a), "l"(b), "l"(d));
}
__device__ __forceinline__ float lo32(unsigned long long a) {
    return __uint_as_float((unsigned)a);
}
__device__ __forceinline__ float hi32(unsigned long long a) {
    return __uint_as_float((unsigned)(a >> 32));
}
__device__ __forceinline__ float p2f(int d) {
    return (d > -126) ? __int_as_float((127 + d) << 23) : 0.f;
}

// ---------------------------------------------------------------------------
// Kernel A: emissions. 4 rows/warp, 8-lane K-split, f32x2 FMA, weight smem
// broadcast-deduped. ALL 24 row-loads batched up-front (128-reg budget) so
// each warp exposes DRAM latency once (MLP=24), then computes from registers.
// ---------------------------------------------------------------------------
__global__ __launch_bounds__(256, 2) void emis_kernel(
    const float* __restrict__ hidden,
    const float* __restrict__ weight,
    const float* __restrict__ bias) {
    __shared__ ulonglong2 ws2[NT * 192];
    __shared__ float bs[NT];

    int tid = threadIdx.x;
    for (int i = tid; i < NT * 192; i += 256)
        ws2[i] = ((const ulonglong2*)weight)[i];
    if (tid < NT) bs[tid] = bias[tid];
    __syncthreads();

    int lane = tid & 31;
    int q = lane >> 3;
    int sub = lane & 7;
    int w = blockIdx.x * 8 + (tid >> 5);
    int r = w * 4 + q;
    int b = r / SL;
    int s = r - b * SL;

    const ulonglong2* hp =
        (const ulonglong2*)(hidden + (size_t)(b * 512 + s + 1) * HID);

    // one fully-batched load burst: 24 x LDG.128, MLP=24
    ulonglong2 h[24];
#pragma unroll
    for (int i = 0; i < 24; i++) h[i] = hp[i * 8 + sub];

    unsigned long long acc2[NT];
#pragma unroll
    for (int t = 0; t < NT; t++) acc2[t] = 0ull;

#pragma unroll
    for (int i = 0; i < 24; i++) {
#pragma unroll
        for (int t = 0; t < NT; t++) {
            ulonglong2 wv = ws2[t * 192 + i * 8 + sub];
            fma2(acc2[t], h[i].x, wv.x);
            fma2(acc2[t], h[i].y, wv.y);
        }
    }

    float acc[NT];
#pragma unroll
    for (int t = 0; t < NT; t++) acc[t] = lo32(acc2[t]) + hi32(acc2[t]);
#pragma unroll
    for (int t = 0; t < NT; t++) {
#pragma unroll
        for (int off = 4; off > 0; off >>= 1)
            acc[t] += __shfl_xor_sync(FULLM, acc[t], off);
    }

    float* o = g_emiss + ((size_t)b * SLP + s) * NT;
#pragma unroll
    for (int t = 0; t < NT; t++) {
        int wsub = (t == 8) ? 0 : t;
        if (sub == wsub) o[t] = acc[t] + bs[t];
    }
}

// ---------------------------------------------------------------------------
// Kernel B: CRF. 128 blocks x 768 threads; blk = 2*b + role (single wave).
//  role 0: plus-times segment matrices -> denominator combine (warp 0)
//          in parallel with numerator (warp 1); atomic final reduce.
//  role 1: max-plus segment matrices -> boundary combine -> exact replay
//          (8 warps) -> backtrack + tag output.
// ---------------------------------------------------------------------------
__global__ __launch_bounds__(768) void crf_kernel(
    const int* __restrict__ labels,
    const float* __restrict__ start_t,
    const float* __restrict__ end_t,
    const float* __restrict__ trans,
    float* __restrict__ out) {
    __shared__ int s_lbl[528];
    __shared__ unsigned char hist[512 * 12];
    __shared__ float s_M[8][108];      // segment matrices (row stride 12)
    __shared__ float s_bnd[8][12];
    __shared__ float s_fin[12];
    __shared__ int s_E[24];
    __shared__ float s_den, s_num;

    int blk = blockIdx.x;
    int b = blk >> 1;
    int role = blk & 1;
    int tid = threadIdx.x;
    int wid = tid >> 5;
    int lane = tid & 31;

    const float* em_base = g_emiss + (size_t)b * SLP * NT;
    const int* lbl = labels + b * 512;

    for (int i = tid; i < 511; i += 768) s_lbl[i] = lbl[i];
    if (tid >= 511 && tid < 528) s_lbl[tid] = -1;
    __syncthreads();

    int seg = wid / 3;
    int tpl = wid - seg * 3;
    int gq = lane / 9;
    int lj9 = lane - gq * 9;
    bool a27 = lane < 27;
    int row = tpl * 3 + gq;
    int gbase = gq * 9;
    int ss0 = 1 + seg * 64;
    bool act = lane < 9;
    int lj = act ? lane : 0;

    if (role == 0) {
        // ========== PHASE A: plus-times row chains (64 steps) =============
        float texp[NT];
#pragma unroll
        for (int k = 0; k < NT; k++) texp[k] = __expf(trans[k * NT + lj9]);
        float st = (a27 && lj9 == row) ? 1.f : 0.f;
        int acc_e = 0;

        float pe_cur[8], em_nxt[8];
#pragma unroll
        for (int u = 0; u < 8; u++)
            pe_cur[u] = __expf(a27 ? em_base[(ss0 + u) * NT + lj9] : -1e30f);
#pragma unroll
        for (int u = 0; u < 8; u++)
            em_nxt[u] = a27 ? em_base[(ss0 + 8 + u) * NT + lj9] : -1e30f;

        for (int gg = 0; gg < 8; ++gg) {
#pragma unroll
            for (int u = 0; u < 8; ++u) {
                int s = ss0 + gg * 8 + u;
                float pe_c = pe_cur[u];
                pe_cur[u] = __expf(em_nxt[u]);
                em_nxt[u] = a27 ? em_base[(s + 16) * NT + lj9] : -1e30f;
                int m = s_lbl[s + 1] >= 0;

                float b0 = __shfl_sync(FULLM, st, gbase + 0);
                float b1 = __shfl_sync(FULLM, st, gbase + 1);
                float b2 = __shfl_sync(FULLM, st, gbase + 2);
                float b3 = __shfl_sync(FULLM, st, gbase + 3);
                float b4 = __shfl_sync(FULLM, st, gbase + 4);
                float b5 = __shfl_sync(FULLM, st, gbase + 5);
                float b6 = __shfl_sync(FULLM, st, gbase + 6);
                float b7 = __shfl_sync(FULLM, st, gbase + 7);
                float b8 = __shfl_sync(FULLM, st, gbase + 8);

                float d0 = fmaf(b6, texp[6], fmaf(b3, texp[3], b0 * texp[0]));
                float d1 = fmaf(b7, texp[7], fmaf(b4, texp[4], b1 * texp[1]));
                float d2 = fmaf(b8, texp[8], fmaf(b5, texp[5], b2 * texp[2]));
                float nv = ((d0 + d1) + d2) * pe_c;
                st = (m && a27) ? nv : st;
            }
            float mx = st;
#pragma unroll
            for (int off = 16; off > 0; off >>= 1)
                mx = fmaxf(mx, __shfl_xor_sync(FULLM, mx, off));
            int Eb = (__float_as_int(mx) >> 23) & 0xff;
            int Es = Eb ? Eb : 127;
            st *= __int_as_float((254 - Es) << 23);
            acc_e += Es - 127;
        }
        if (a27) s_M[seg][row * 12 + lj9] = st;
        if (lane == 0) s_E[seg * 3 + tpl] = acc_e;
        __syncthreads();

        // ========== COMBINE (warp 0) || NUMERATOR (warp 1) ================
        if (wid == 0) {
            float v = act ? __expf(start_t[lane] + em_base[lane]) : 0.f;
            int acc = 0;
            for (int sg = 0; sg < 8; ++sg) {
                float vi[9];
#pragma unroll
                for (int i = 0; i < 9; i++) vi[i] = __shfl_sync(FULLM, v, i);
                const float* M = s_M[sg];
                float q0 = vi[0]*M[0*12+lj] + vi[1]*M[1*12+lj] + vi[2]*M[2*12+lj];
                float q1 = vi[3]*M[3*12+lj] + vi[4]*M[4*12+lj] + vi[5]*M[5*12+lj];
                float q2 = vi[6]*M[6*12+lj] + vi[7]*M[7*12+lj] + vi[8]*M[8*12+lj];
                int E0 = s_E[sg*3+0], E1 = s_E[sg*3+1], E2 = s_E[sg*3+2];
                int Em = max(E0, max(E1, E2));
                float nv = q0 * p2f(E0 - Em) + q1 * p2f(E1 - Em)
                         + q2 * p2f(E2 - Em);
                acc += Em;
                float ref = __shfl_sync(FULLM, nv, 4);
                int Rb = (__float_as_int(ref) >> 23) & 0xff;
                int Rs = Rb ? Rb : 127;
                nv *= __int_as_float((254 - Rs) << 23);
                acc += Rs - 127;
                v = act ? nv : 0.f;
            }
            float fa = act ? v * __expf(end_t[lane]) : 0.f;
            fa += __shfl_xor_sync(FULLM, fa, 8);
            fa += __shfl_xor_sync(FULLM, fa, 4);
            fa += __shfl_xor_sync(FULLM, fa, 2);
            fa += __shfl_xor_sync(FULLM, fa, 1);
            if (lane == 0)
                s_den = __logf(fa) + (float)acc * 0.69314718056f;
        } else if (wid == 1) {
            int t0 = lane * 16;
            float sum = 0.f;
            int prev = -1, ftag = -1;
            for (int k = 0; k < 16; ++k) {
                int t = t0 + k;
                if (t == 0 || t > 509) continue;
                int lv = s_lbl[t + 1];
                if (lv >= 0) {
                    sum += em_base[t * NT + lv];
                    if (prev >= 0) sum += trans[prev * NT + lv];
                    else ftag = lv;
                    prev = lv;
                }
            }
            int l1 = s_lbl[1];
            int tag0 = (l1 >= 0) ? l1 : 0;

            int x = prev;
#pragma unroll
            for (int off = 1; off < 32; off <<= 1) {
                int y = __shfl_up_sync(FULLM, x, off);
                if (lane >= off && x < 0) x = y;
            }
            int excl = __shfl_up_sync(FULLM, x, 1);
            int carry = (lane == 0 || excl < 0) ? tag0 : excl;

            if (ftag >= 0) sum += trans[carry * NT + ftag];
            if (lane == 0) sum += start_t[tag0] + em_base[tag0];
            if (lane == 31) sum += end_t[(x < 0) ? tag0 : x];

#pragma unroll
            for (int off = 16; off > 0; off >>= 1)
                sum += __shfl_xor_sync(FULLM, sum, off);
            if (lane == 0) s_num = sum;
        }
        __syncthreads();

        if (tid == 0) {
            g_val[b] = s_num - s_den;
            __threadfence();
            unsigned old = atomicAdd(&g_cnt, 1u);
            if (old == NB - 1) {
                __threadfence();
                float sum = 0.f;
                const volatile float* gv = g_val;
#pragma unroll
                for (int i = 0; i < NB; i++) sum += gv[i];
                out[0] = -sum;
                atomicSub(&g_cnt, (unsigned)NB);   // restore for next launch
            }
        }
    } else {
        // ========== PHASE A: max-plus row chains (64 steps) ===============
        float tra[NT];
#pragma unroll
        for (int k = 0; k < NT; k++) tra[k] = trans[k * NT + lj9];
        float st = (a27 && lj9 == row) ? 0.f : -1e30f;

        float em_r[8];
#pragma unroll
        for (int u = 0; u < 8; u++)
            em_r[u] = a27 ? em_base[(ss0 + u) * NT + lj9] : 0.f;

        for (int gg = 0; gg < 8; ++gg) {
#pragma unroll
            for (int u = 0; u < 8; ++u) {
                int s = ss0 + gg * 8 + u;
                float em_c = em_r[u];
                em_r[u] = a27 ? em_base[(s + 8) * NT + lj9] : 0.f;
                int m = s_lbl[s + 1] >= 0;

                float x0 = __shfl_sync(FULLM, st, gbase + 0) + tra[0];
                float x1 = __shfl_sync(FULLM, st, gbase + 1) + tra[1];
                float x2 = __shfl_sync(FULLM, st, gbase + 2) + tra[2];
                float x3 = __shfl_sync(FULLM, st, gbase + 3) + tra[3];
                float x4 = __shfl_sync(FULLM, st, gbase + 4) + tra[4];
                float x5 = __shfl_sync(FULLM, st, gbase + 5) + tra[5];
                float x6 = __shfl_sync(FULLM, st, gbase + 6) + tra[6];
                float x7 = __shfl_sync(FULLM, st, gbase + 7) + tra[7];
                float x8 = __shfl_sync(FULLM, st, gbase + 8) + tra[8];

                float mA = fmaxf(fmaxf(fmaxf(x0, x1), fmaxf(x2, x3)),
                                 fmaxf(fmaxf(x4, x5), fmaxf(x6, fmaxf(x7, x8))));
                st = (m && a27) ? (mA + em_c) : st;
            }
        }
        if (a27) s_M[seg][row * 12 + lj9] = st;
        __syncthreads();

        // ========== COMBINE: boundary vectors (warp 0) ====================
        if (wid == 0) {
            float v = act ? (start_t[lane] + em_base[lane]) : -1e30f;
            if (act) s_bnd[0][lane] = v;
            for (int sg = 0; sg < 8; ++sg) {
                float vi[9];
#pragma unroll
                for (int i = 0; i < 9; i++) vi[i] = __shfl_sync(FULLM, v, i);
                const float* M = s_M[sg];
                float c0 = fmaxf(vi[0] + M[0*12+lj], vi[1] + M[1*12+lj]);
                float c1 = fmaxf(vi[2] + M[2*12+lj], vi[3] + M[3*12+lj]);
                float c2 = fmaxf(vi[4] + M[4*12+lj], vi[5] + M[5*12+lj]);
                float c3 = fmaxf(vi[6] + M[6*12+lj],
                          fmaxf(vi[7] + M[7*12+lj], vi[8] + M[8*12+lj]));
                float nv = fmaxf(fmaxf(c0, c1), fmaxf(c2, c3));
                v = act ? nv : -1e30f;
                if (act && sg < 7) s_bnd[sg + 1][lane] = v;
            }
        }
        __syncthreads();

        // ========== REPLAY (8 warps, bitwise-exact) =======================
        if (wid < 8) {
            int sg = wid;
            int ss = 1 + sg * 64;
            float tr[NT];
#pragma unroll
            for (int k = 0; k < NT; k++) tr[k] = trans[k * NT + lj];
            float vs = act ? s_bnd[sg][lane] : -1e30f;

            float em2[8];
#pragma unroll
            for (int u = 0; u < 8; u++)
                em2[u] = act ? em_base[(ss + u) * NT + lane] : 0.f;

            for (int gg = 0; gg < 8; ++gg) {
#pragma unroll
                for (int u = 0; u < 8; ++u) {
                    int s = ss + gg * 8 + u;
                    float em_c = em2[u];
                    em2[u] = act ? em_base[(s + 8) * NT + lane] : 0.f;
                    int m = s_lbl[s + 1] >= 0;

                    float x0 = __shfl_sync(FULLM, vs, 0) + tr[0];
                    float x1 = __shfl_sync(FULLM, vs, 1) + tr[1];
                    float x2 = __shfl_sync(FULLM, vs, 2) + tr[2];
                    float x3 = __shfl_sync(FULLM, vs, 3) + tr[3];
                    float x4 = __shfl_sync(FULLM, vs, 4) + tr[4];
                    float x5 = __shfl_sync(FULLM, vs, 5) + tr[5];
                    float x6 = __shfl_sync(FULLM, vs, 6) + tr[6];
                    float x7 = __shfl_sync(FULLM, vs, 7) + tr[7];
                    float x8 = __shfl_sync(FULLM, vs, 8) + tr[8];

                    float mA = fmaxf(fmaxf(fmaxf(x0, x1), fmaxf(x2, x3)),
                                     fmaxf(fmaxf(x4, x5),
                                           fmaxf(x6, fmaxf(x7, x8))));
                    vs = (m && act) ? (mA + em_c) : vs;

                    int bi = 8;
                    if (x7 == mA) bi = 7;
                    if (x6 == mA) bi = 6;
                    if (x5 == mA) bi = 5;
                    if (x4 == mA) bi = 4;
                    if (x3 == mA) bi = 3;
                    if (x2 == mA) bi = 2;
                    if (x1 == mA) bi = 1;
                    if (x0 == mA) bi = 0;

                    if (act)
                        hist[(s - 1) * 12 + lane] =
                            (unsigned char)(m ? bi : lane);
                }
            }
            if (sg == 7 && act) s_fin[lane] = vs;
        }
        __syncthreads();

        // ========== FINALIZE (warp 0): argmax + backtrack =================
        if (wid == 0) {
            float fv = act ? (s_fin[lane] + end_t[lane]) : -1e30f;
            int fi = act ? lane : 15;
#pragma unroll
            for (int off = 8; off > 0; off >>= 1) {
                float ov = __shfl_xor_sync(FULLM, fv, off);
                int oi = __shfl_xor_sync(FULLM, fi, off);
                bool take = (ov > fv) || (ov == fv && oi < fi);
                fv = take ? ov : fv;
                fi = take ? oi : fi;
            }
            int last = __shfl_sync(FULLM, fi, 0);
            __syncwarp();

            int a = lane * 16;
            int bnd2 = a + 16 < (SL - 1) ? a + 16 : (SL - 1);
            unsigned long long F = 0x876543210ull;
            for (int s = bnd2 - 1; s >= a; --s) {
                const unsigned char* hr = hist + s * 12;
                unsigned long long nF = 0;
#pragma unroll
                for (int t = 0; t < NT; t++) {
                    int e = (int)((F >> (4 * t)) & 15);
                    nF |= ((unsigned long long)hr[e]) << (4 * t);
                }
                F = nF;
            }
            unsigned int flo = (unsigned int)F, fhi = (unsigned int)(F >> 32);
            int cur = last;
            int my_entry = (lane == 31) ? last : 0;
            for (int l = 31; l >= 1; --l) {
                unsigned int lo = __shfl_sync(FULLM, flo, l);
                unsigned int hi = __shfl_sync(FULLM, fhi, l);
                unsigned long long Fl = ((unsigned long long)hi << 32) | lo;
                cur = (int)((Fl >> (4 * cur)) & 15);
                if (lane == l - 1) my_entry = cur;
            }

            float* otag = out + 1 + (size_t)b * SL;
            if (lane == 31)
                otag[SL - 1] = (s_lbl[SL] >= 0) ? (float)last : 0.f;
            int c2 = my_entry;
            for (int s = bnd2 - 1; s >= a; --s) {
                c2 = hist[s * 12 + c2];
                otag[s] = (s_lbl[s + 1] >= 0) ? (float)c2 : 0.f;
            }
        }
    }
}

// ---------------------------------------------------------------------------
extern "C" void kernel_launch(void* const* d_in, const int* in_sizes, int n_in,
                              void* d_out, int out_size) {
    const float* hidden  = (const float*)d_in[0];
    const int*   labels  = (const int*)d_in[1];
    const float* weight  = (const float*)d_in[2];
    const float* bias    = (const float*)d_in[3];
    const float* start_t = (const float*)d_in[4];
    const float* end_t   = (const float*)d_in[5];
    const float* trans   = (const float*)d_in[6];
    float* out = (float*)d_out;

    emis_kernel<<<1020, 256>>>(hidden, weight, bias);
    crf_kernel<<<2 * NB, 768>>>(labels, start_t, end_t, trans, out);
}